// round 2
// baseline (speedup 1.0000x reference)
#include <cuda_runtime.h>

// 16-qubit real-statevector simulator, bsz=256.
// qubit q <-> bit (15-q) of the flattened index (qubit 0 = MSB).
// State is real: RY + CNOT + |0> keep psi real; Im(H) cancels in <psi|H|psi>.

#define NQ      16
#define NSTATE  65536
#define BSZ     256
#define TILE    8192
#define THREADS 256
#define NOBS    15

__device__ float g_state[(size_t)BSZ * NSTATE];     // 64 MB, real amplitudes
__device__ float g_part[BSZ * NOBS * 8];            // per-(batch,obs,tile) partial sums

// ---------------- gate primitives on an smem tile of TILE floats ----------------

__device__ __forceinline__ void ry_gate(float* t, int p, float c, float s) {
    const int tid = threadIdx.x;
    const int mask = (1 << p) - 1;
    #pragma unroll 4
    for (int m = tid; m < TILE / 2; m += THREADS) {
        int i0 = ((m & ~mask) << 1) | (m & mask);
        int i1 = i0 | (1 << p);
        float a0 = t[i0], a1 = t[i1];
        t[i0] = c * a0 - s * a1;
        t[i1] = s * a0 + c * a1;
    }
    __syncthreads();
}

// CNOT: control bit pc, target bit pt (swap target pair on control==1 slice)
__device__ __forceinline__ void cnot_gate(float* t, int pc, int pt) {
    const int tid = threadIdx.x;
    const int ph = pc > pt ? pc : pt;
    const int pl = pc > pt ? pt : pc;
    const int ml = (1 << pl) - 1;
    const int mh = (1 << ph) - 1;
    #pragma unroll 4
    for (int m = tid; m < TILE / 4; m += THREADS) {
        int x = ((m & ~ml) << 1) | (m & ml);
        x = ((x & ~mh) << 1) | (x & mh);
        int i0 = x | (1 << pc);      // control=1, target=0
        int i1 = i0 | (1 << pt);     // control=1, target=1
        float v0 = t[i0];
        t[i0] = t[i1];
        t[i1] = v0;
    }
    __syncthreads();
}

// angle for (layer, qubit). Effective layers 0..6:
// 0..2: encoding blocks 0..2;  3: enc block 3 + VQC layer 0 (RY angles add);
// 4..6: VQC layers 1..3.  All 7 effective layers end with a full CNOT ladder.
__device__ __forceinline__ float layer_theta(const float* x, const float* var,
                                             int b, int layer, int q) {
    if (layer <= 2)      return x[b * 64 + layer * 16 + q];
    else if (layer == 3) return x[b * 64 + 48 + q] + var[q];
    else                 return var[(layer - 3) * 16 + q];
}

// ---------------- pass A: tile = contiguous bits 0..12 (qubits 3..15) ----------------

__global__ void __launch_bounds__(THREADS)
pass_a(const float* __restrict__ x, const float* __restrict__ var, int layer, int init) {
    __shared__ __align__(16) float t[TILE];
    __shared__ float cs[NQ][2];
    const int b = blockIdx.x >> 3;
    const int f = blockIdx.x & 7;
    const int tid = threadIdx.x;

    if (tid < NQ) {
        float th = layer_theta(x, var, b, layer, tid);
        cs[tid][0] = cosf(0.5f * th);
        cs[tid][1] = sinf(0.5f * th);
    }
    __syncthreads();

    float* g = g_state + (size_t)b * NSTATE + f * TILE;

    if (init) {
        // product state after layer-0 RYs: amp = prod_q r_q(bit), r(0)=cos, r(1)=sin
        float pre = cs[0][(f >> 2) & 1] * cs[1][(f >> 1) & 1] * cs[2][f & 1];
        for (int j = tid; j < TILE; j += THREADS) {
            float a = pre;
            #pragma unroll
            for (int bit = 0; bit < 13; bit++)
                a *= cs[15 - bit][(j >> bit) & 1];
            t[j] = a;
        }
        __syncthreads();
    } else {
        float4* t4 = (float4*)t;
        const float4* g4 = (const float4*)g;
        for (int j = tid; j < TILE / 4; j += THREADS) t4[j] = g4[j];
        __syncthreads();
        for (int q = 3; q <= 15; q++)
            ry_gate(t, 15 - q, cs[q][0], cs[q][1]);
    }

    // even ladder within qubits 3..15: (4,5)(6,7)(8,9)(10,11)(12,13)(14,15)
    cnot_gate(t, 11, 10);
    cnot_gate(t, 9, 8);
    cnot_gate(t, 7, 6);
    cnot_gate(t, 5, 4);
    cnot_gate(t, 3, 2);
    cnot_gate(t, 1, 0);
    // odd ladder within: (5,6)(7,8)(9,10)(11,12)(13,14)
    cnot_gate(t, 10, 9);
    cnot_gate(t, 8, 7);
    cnot_gate(t, 6, 5);
    cnot_gate(t, 4, 3);
    cnot_gate(t, 2, 1);

    float4* t4 = (float4*)t;
    float4* g4w = (float4*)g;
    for (int j = tid; j < TILE / 4; j += THREADS) g4w[j] = t4[j];
}

// ---------------- pass B: tile = bits {0..7} U {11..15}, fixed bits 8..10 = f ------
// local j: bits 0..7 -> global 0..7; bits 8..12 -> global 11..15
// float4 map: gi4 = ((j4>>6)<<9) | (f<<6) | (j4&63)

__global__ void __launch_bounds__(THREADS)
pass_b(const float* __restrict__ x, const float* __restrict__ var, int layer, int skip_ry) {
    __shared__ __align__(16) float t[TILE];
    __shared__ float cs[3][2];
    const int b = blockIdx.x >> 3;
    const int f = blockIdx.x & 7;
    const int tid = threadIdx.x;

    if (tid < 3) {
        float th = layer_theta(x, var, b, layer, tid);
        cs[tid][0] = cosf(0.5f * th);
        cs[tid][1] = sinf(0.5f * th);
    }
    __syncthreads();

    float4* t4 = (float4*)t;
    const float4* g4 = (const float4*)(g_state + (size_t)b * NSTATE);
    for (int j = tid; j < TILE / 4; j += THREADS) {
        int gi = ((j >> 6) << 9) | (f << 6) | (j & 63);
        t4[j] = g4[gi];
    }
    __syncthreads();

    if (!skip_ry) {             // layer 0: RY(0..2) already folded into product init
        ry_gate(t, 12, cs[0][0], cs[0][1]);   // RY(q0) @ global bit 15 -> j bit 12
        ry_gate(t, 11, cs[1][0], cs[1][1]);   // RY(q1)
        ry_gate(t, 10, cs[2][0], cs[2][1]);   // RY(q2)
    }
    cnot_gate(t, 12, 11);   // CNOT(0,1)  [even ladder]
    cnot_gate(t, 10, 9);    // CNOT(2,3)  [even ladder]
    cnot_gate(t, 11, 10);   // CNOT(1,2)  [odd ladder]
    cnot_gate(t, 9, 8);     // CNOT(3,4)  [odd ladder]

    float4* g4w = (float4*)(g_state + (size_t)b * NSTATE);
    for (int j = tid; j < TILE / 4; j += THREADS) {
        int gi = ((j >> 6) << 9) | (f << 6) | (j & 63);
        g4w[gi] = t4[j];
    }
}

// ---------------- measurement ----------------
// E_w = sum over groups: 2*D1*p0^2 + 2*D2*p1^2 + 2*D3*p2^2
//       + 2*(A0 p1 p0 + A1 p2 p0 + A2 p2 p1 + A3 p3 p0 + A4 p3 p1 + A5 p3 p2)
// with k = 2*bit(qubit w) + bit(qubit w+1).  B cancels (psi real).

__device__ __forceinline__ void obs_accum_store(const float* t,
                                                const float* __restrict__ A,
                                                const float* __restrict__ D,
                                                int w, int bhi, int b, int f,
                                                float* red) {
    const int tid = threadIdx.x;
    const int blo = bhi - 1;
    const float a0 = A[w * 6 + 0], a1 = A[w * 6 + 1], a2 = A[w * 6 + 2];
    const float a3 = A[w * 6 + 3], a4 = A[w * 6 + 4], a5 = A[w * 6 + 5];
    const float d1 = 2.f * D[w * 4 + 1], d2 = 2.f * D[w * 4 + 2], d3 = 2.f * D[w * 4 + 3];
    const int ml = (1 << blo) - 1;
    float acc = 0.f;
    #pragma unroll 4
    for (int m = tid; m < TILE / 4; m += THREADS) {
        int i00 = ((m & ~ml) << 2) | (m & ml);
        float p0 = t[i00];
        float p1 = t[i00 + (1 << blo)];
        float p2 = t[i00 + (1 << bhi)];
        float p3 = t[i00 + (1 << bhi) + (1 << blo)];
        acc += d1 * p0 * p0 + d2 * p1 * p1 + d3 * p2 * p2
             + 2.f * (a0 * p1 * p0 + a1 * p2 * p0 + a2 * p2 * p1
                    + a3 * p3 * p0 + a4 * p3 * p1 + a5 * p3 * p2);
    }
    #pragma unroll
    for (int off = 16; off > 0; off >>= 1)
        acc += __shfl_down_sync(0xffffffffu, acc, off);
    if ((tid & 31) == 0) red[tid >> 5] = acc;
    __syncthreads();
    if (tid == 0) {
        float s = 0.f;
        #pragma unroll
        for (int wg = 0; wg < THREADS / 32; wg++) s += red[wg];
        g_part[(b * NOBS + w) * 8 + f] = s;   // deterministic, no atomics
    }
    __syncthreads();
}

__global__ void __launch_bounds__(THREADS)
measure_a(const float* __restrict__ A, const float* __restrict__ D) {
    __shared__ __align__(16) float t[TILE];
    __shared__ float red[THREADS / 32];
    const int b = blockIdx.x >> 3;
    const int f = blockIdx.x & 7;
    const int tid = threadIdx.x;
    const float4* g4 = (const float4*)(g_state + (size_t)b * NSTATE + f * TILE);
    float4* t4 = (float4*)t;
    for (int j = tid; j < TILE / 4; j += THREADS) t4[j] = g4[j];
    __syncthreads();
    // obs w=3..14: qubit pair (w,w+1) -> tile bits (15-w, 14-w)
    for (int w = 3; w <= 14; w++)
        obs_accum_store(t, A, D, w, 15 - w, b, f, red);
}

__global__ void __launch_bounds__(THREADS)
measure_b(const float* __restrict__ A, const float* __restrict__ D) {
    __shared__ __align__(16) float t[TILE];
    __shared__ float red[THREADS / 32];
    const int b = blockIdx.x >> 3;
    const int f = blockIdx.x & 7;
    const int tid = threadIdx.x;
    const float4* g4 = (const float4*)(g_state + (size_t)b * NSTATE);
    float4* t4 = (float4*)t;
    for (int j = tid; j < TILE / 4; j += THREADS) {
        int gi = ((j >> 6) << 9) | (f << 6) | (j & 63);
        t4[j] = g4[gi];
    }
    __syncthreads();
    // obs w=0..2: global bits (15-w,14-w) -> pass-B local bits (12-w, 11-w)
    for (int w = 0; w <= 2; w++)
        obs_accum_store(t, A, D, w, 12 - w, b, f, red);
}

// ---------------- head: out[b,o] = sum_w qout[b,w] * hw[o,w] + hb[o] ----------------

__global__ void __launch_bounds__(THREADS)
head_kernel(const float* __restrict__ hw, const float* __restrict__ hb,
            float* __restrict__ out) {
    const int i = blockIdx.x * blockDim.x + threadIdx.x;   // 16384 threads
    const int b = i >> 6;
    const int o = i & 63;
    float acc = hb[o];
    #pragma unroll
    for (int w = 0; w < NOBS; w++) {
        float e = 0.f;
        #pragma unroll
        for (int f = 0; f < 8; f++) e += g_part[(b * NOBS + w) * 8 + f];
        acc += e * hw[o * NOBS + w];
    }
    out[i] = acc;
}

// ---------------- launcher ----------------

extern "C" void kernel_launch(void* const* d_in, const int* in_sizes, int n_in,
                              void* d_out, int out_size) {
    const float* x   = (const float*)d_in[0];   // (256,64)
    const float* A   = (const float*)d_in[1];   // (15,6)
    // d_in[2] = B: unused (imaginary part cancels for a real state)
    const float* D   = (const float*)d_in[3];   // (15,4)
    const float* var = (const float*)d_in[4];   // (4,16)
    const float* hw  = (const float*)d_in[5];   // (64,15)
    const float* hb  = (const float*)d_in[6];   // (64,)
    float* out = (float*)d_out;                 // (256,64)

    const int GRID = BSZ * 8;                   // 2048 CTAs per pass

    // layer 0: product-state init (all 16 RYs folded in) + ladder
    pass_a<<<GRID, THREADS>>>(x, var, 0, 1);
    pass_b<<<GRID, THREADS>>>(x, var, 0, 1);
    // layers 1..6 (enc1, enc2, enc3+vqc0 merged, vqc1, vqc2, vqc3)
    for (int L = 1; L <= 6; L++) {
        pass_a<<<GRID, THREADS>>>(x, var, L, 0);
        pass_b<<<GRID, THREADS>>>(x, var, L, 0);
    }

    measure_a<<<GRID, THREADS>>>(A, D);
    measure_b<<<GRID, THREADS>>>(A, D);
    head_kernel<<<64, THREADS>>>(hw, hb, out);
}

// round 3
// speedup vs baseline: 2.3900x; 2.3900x over previous
#include <cuda_runtime.h>

// 16-qubit real-statevector simulator, bsz=256, register-blocked gates.
// qubit q <-> bit (15-q) of the flattened index (qubit 0 = MSB).
// State stays real (RY + CNOT + |0>); Im(H) cancels in <psi|H|psi> so B is unused.

#define NQ      16
#define NSTATE  65536
#define BSZ     256
#define TILE    8192
#define THREADS 256
#define NOBS    15

// bank-conflict-free smem swizzle for all three stage tilings
#define SW(j) ((j) ^ (((j) >> 5) & 31))

__device__ float g_state[(size_t)BSZ * NSTATE];   // 64 MB real amplitudes
__device__ float g_part[BSZ * NOBS * 8];          // per-(batch,obs,tile) partials

// ---------------- register-resident gate primitives (32 amps / thread) ----------------

template<int BIT>
__device__ __forceinline__ void ry_reg(float* v, float c, float s) {
    #pragma unroll
    for (int m = 0; m < 16; m++) {
        const int i0 = ((m >> BIT) << (BIT + 1)) | (m & ((1 << BIT) - 1));
        const int i1 = i0 | (1 << BIT);
        float a0 = v[i0], a1 = v[i1];
        v[i0] = c * a0 - s * a1;
        v[i1] = s * a0 + c * a1;
    }
}

template<int PC, int PT>
__device__ __forceinline__ void cnot_reg(float* v) {
    constexpr int PH = PC > PT ? PC : PT;
    constexpr int PL = PC > PT ? PT : PC;
    #pragma unroll
    for (int m = 0; m < 8; m++) {
        int x = ((m >> PL) << (PL + 1)) | (m & ((1 << PL) - 1));
        x = ((x >> PH) << (PH + 1)) | (x & ((1 << PH) - 1));
        const int i0 = x | (1 << PC);
        const int i1 = i0 | (1 << PT);
        float tmp = v[i0]; v[i0] = v[i1]; v[i1] = tmp;
    }
}

// quadratic form for one observable over register pair bits (BHI, BHI-1)
template<int BHI>
__device__ __forceinline__ float obs_reg(const float* v,
                                         const float* __restrict__ A,
                                         const float* __restrict__ D, int w) {
    constexpr int BLO = BHI - 1;
    const float a0 = A[w*6+0], a1 = A[w*6+1], a2 = A[w*6+2];
    const float a3 = A[w*6+3], a4 = A[w*6+4], a5 = A[w*6+5];
    const float d1 = 2.f*D[w*4+1], d2 = 2.f*D[w*4+2], d3 = 2.f*D[w*4+3];
    float acc = 0.f;
    #pragma unroll
    for (int m = 0; m < 8; m++) {
        int x = ((m >> BLO) << (BLO + 1)) | (m & ((1 << BLO) - 1));
        x = ((x >> BHI) << (BHI + 1)) | (x & ((1 << BHI) - 1));
        float p0 = v[x];
        float p1 = v[x | (1 << BLO)];
        float p2 = v[x | (1 << BHI)];
        float p3 = v[x | (1 << BHI) | (1 << BLO)];
        acc += d1*p0*p0 + d2*p1*p1 + d3*p2*p2
             + 2.f*(a0*p1*p0 + a1*p2*p0 + a2*p2*p1
                  + a3*p3*p0 + a4*p3*p1 + a5*p3*p2);
    }
    return acc;
}

__device__ __forceinline__ float wred(float a) {
    #pragma unroll
    for (int o = 16; o; o >>= 1) a += __shfl_down_sync(0xffffffffu, a, o);
    return a;
}

// angle for (effective layer, qubit). Layers 0..6:
// 0..2: enc blocks 0..2;  3: enc block 3 + VQC layer 0 (angles add);  4..6: VQC 1..3.
__device__ __forceinline__ float layer_theta(const float* x, const float* var,
                                             int b, int layer, int q) {
    if (layer <= 2)      return x[b * 64 + layer * 16 + q];
    else if (layer == 3) return x[b * 64 + 48 + q] + var[q];
    else                 return var[(layer - 3) * 16 + q];
}

// ---------------- pass A: tile = contiguous bits 0..12 (qubits 3..15) ----------------
// 3 register stages; tile bit p <-> qubit 15-p.

__global__ void __launch_bounds__(THREADS)
pass_a(const float* __restrict__ x, const float* __restrict__ var, int layer, int init) {
    __shared__ __align__(16) float t[TILE];
    __shared__ float cs[NQ][2];
    const int b = blockIdx.x >> 3;
    const int f = blockIdx.x & 7;
    const int tid = threadIdx.x;

    if (tid < NQ) {
        float th = layer_theta(x, var, b, layer, tid);
        cs[tid][0] = cosf(0.5f * th);
        cs[tid][1] = sinf(0.5f * th);
    }
    __syncthreads();

    float* g = g_state + (size_t)b * NSTATE + f * TILE;
    float v[32];

    // ---- stage 1: register bits {12..8} = qubits 3..7; thread bits = tile bits 7..0
    if (init) {
        // product state after the 16 layer-0 RYs
        float pre = cs[0][(f >> 2) & 1] * cs[1][(f >> 1) & 1] * cs[2][f & 1];
        #pragma unroll
        for (int i = 0; i < 8; i++) pre *= cs[15 - i][(tid >> i) & 1];
        #pragma unroll
        for (int r = 0; r < 32; r++) {
            float a = pre;
            #pragma unroll
            for (int k = 0; k < 5; k++) a *= cs[7 - k][(r >> k) & 1];
            v[r] = a;
        }
    } else {
        #pragma unroll
        for (int r = 0; r < 32; r++) v[r] = g[(r << 8) | tid];
        ry_reg<4>(v, cs[3][0], cs[3][1]);
        ry_reg<3>(v, cs[4][0], cs[4][1]);
        ry_reg<2>(v, cs[5][0], cs[5][1]);
        ry_reg<1>(v, cs[6][0], cs[6][1]);
        ry_reg<0>(v, cs[7][0], cs[7][1]);
    }
    cnot_reg<3, 2>(v);   // CNOT(4,5)  tile bits (11,10)  [even]
    cnot_reg<1, 0>(v);   // CNOT(6,7)  (9,8)              [even]
    cnot_reg<2, 1>(v);   // CNOT(5,6)  (10,9)             [odd]
    #pragma unroll
    for (int r = 0; r < 32; r++) t[SW((r << 8) | tid)] = v[r];
    __syncthreads();

    // ---- stage 2: register bits {8..4}; thread bits = tile bits 12..9 and 3..0
    {
        const int base = ((tid >> 4) << 9) | (tid & 15);
        #pragma unroll
        for (int r = 0; r < 32; r++) v[r] = t[SW(base | (r << 4))];
        if (!init) {
            ry_reg<3>(v, cs[8][0],  cs[8][1]);    // qubit 8  (bit 7)
            ry_reg<2>(v, cs[9][0],  cs[9][1]);    // qubit 9
            ry_reg<1>(v, cs[10][0], cs[10][1]);   // qubit 10
            ry_reg<0>(v, cs[11][0], cs[11][1]);   // qubit 11 (bit 4)
        }
        cnot_reg<3, 2>(v);   // CNOT(8,9)   bits (7,6) [even]
        cnot_reg<1, 0>(v);   // CNOT(10,11) bits (5,4) [even]
        cnot_reg<4, 3>(v);   // CNOT(7,8)   bits (8,7) [odd, after (9,8)&(7,6)]
        cnot_reg<2, 1>(v);   // CNOT(9,10)  bits (6,5) [odd]
        #pragma unroll
        for (int r = 0; r < 32; r++) t[SW(base | (r << 4))] = v[r];
    }
    __syncthreads();

    // ---- stage 3: register bits {4..0}; thread bits = tile bits 12..5
    {
        #pragma unroll
        for (int r = 0; r < 32; r++) v[r] = t[SW((tid << 5) | r)];
        if (!init) {
            ry_reg<3>(v, cs[12][0], cs[12][1]);   // qubit 12 (bit 3)
            ry_reg<2>(v, cs[13][0], cs[13][1]);   // qubit 13
            ry_reg<1>(v, cs[14][0], cs[14][1]);   // qubit 14
            ry_reg<0>(v, cs[15][0], cs[15][1]);   // qubit 15 (bit 0)
        }
        cnot_reg<3, 2>(v);   // CNOT(12,13) bits (3,2) [even]
        cnot_reg<1, 0>(v);   // CNOT(14,15) bits (1,0) [even]
        cnot_reg<4, 3>(v);   // CNOT(11,12) bits (4,3) [odd, after (5,4)&(3,2)]
        cnot_reg<2, 1>(v);   // CNOT(13,14) bits (2,1) [odd]
        float4* g4 = (float4*)(g + (tid << 5));
        #pragma unroll
        for (int i = 0; i < 8; i++)
            g4[i] = make_float4(v[4*i], v[4*i+1], v[4*i+2], v[4*i+3]);
    }
}

// ---------------- pass B: pure-register kernel on global bits {15..11} ----------------
// register bit k <-> global bit 11+k; rest (bits 10..0) = (sub<<8)|tid.
// Gates: RY(q0,q1,q2) -> reg bits 4,3,2;  CNOT(0,1)->(4,3), (2,3)->(2,1) [even],
//        CNOT(1,2)->(3,2), (3,4)->(1,0) [odd].  Final layer also computes obs 0..2.

__global__ void __launch_bounds__(THREADS)
pass_b(const float* __restrict__ x, const float* __restrict__ var,
       const float* __restrict__ A, const float* __restrict__ D,
       int layer, int init, int measure) {
    __shared__ float red[3][8];
    const int b = blockIdx.x >> 3;
    const int sub = blockIdx.x & 7;
    const int tid = threadIdx.x;
    const int rest = (sub << 8) | tid;

    float* g = g_state + (size_t)b * NSTATE + rest;
    float v[32];
    #pragma unroll
    for (int r = 0; r < 32; r++) v[r] = g[r << 11];

    if (!init) {
        float t0 = layer_theta(x, var, b, layer, 0);
        float t1 = layer_theta(x, var, b, layer, 1);
        float t2 = layer_theta(x, var, b, layer, 2);
        ry_reg<4>(v, cosf(0.5f * t0), sinf(0.5f * t0));
        ry_reg<3>(v, cosf(0.5f * t1), sinf(0.5f * t1));
        ry_reg<2>(v, cosf(0.5f * t2), sinf(0.5f * t2));
    }
    cnot_reg<4, 3>(v);   // CNOT(0,1) [even]
    cnot_reg<2, 1>(v);   // CNOT(2,3) [even]
    cnot_reg<3, 2>(v);   // CNOT(1,2) [odd]
    cnot_reg<1, 0>(v);   // CNOT(3,4) [odd]

    #pragma unroll
    for (int r = 0; r < 32; r++) g[r << 11] = v[r];

    if (measure) {
        // obs w=0..2 use global bits (15-w,14-w) -> reg bits (4-w,3-w)
        float a0 = wred(obs_reg<4>(v, A, D, 0));
        float a1 = wred(obs_reg<3>(v, A, D, 1));
        float a2 = wred(obs_reg<2>(v, A, D, 2));
        if ((tid & 31) == 0) {
            red[0][tid >> 5] = a0;
            red[1][tid >> 5] = a1;
            red[2][tid >> 5] = a2;
        }
        __syncthreads();
        if (tid < 3) {
            float s = 0.f;
            #pragma unroll
            for (int wg = 0; wg < 8; wg++) s += red[tid][wg];
            g_part[(b * NOBS + tid) * 8 + sub] = s;
        }
    }
}

// ---------------- measurement: obs 3..14, register-staged over contiguous tile ------

__global__ void __launch_bounds__(THREADS)
measure_a(const float* __restrict__ A, const float* __restrict__ D) {
    __shared__ __align__(16) float t[TILE];
    __shared__ float red[12][8];
    const int b = blockIdx.x >> 3;
    const int f = blockIdx.x & 7;
    const int tid = threadIdx.x;
    const int warp = tid >> 5;
    const int lane = tid & 31;
    const float* g = g_state + (size_t)b * NSTATE + f * TILE;
    float v[32];

    // stage 1: register bits {12..8} -> obs 3..6 (tile-bit pairs (12,11)..(9,8))
    #pragma unroll
    for (int r = 0; r < 32; r++) v[r] = g[(r << 8) | tid];
    {
        float s3 = wred(obs_reg<4>(v, A, D, 3));
        float s4 = wred(obs_reg<3>(v, A, D, 4));
        float s5 = wred(obs_reg<2>(v, A, D, 5));
        float s6 = wred(obs_reg<1>(v, A, D, 6));
        if (lane == 0) { red[0][warp]=s3; red[1][warp]=s4; red[2][warp]=s5; red[3][warp]=s6; }
    }
    #pragma unroll
    for (int r = 0; r < 32; r++) t[SW((r << 8) | tid)] = v[r];
    __syncthreads();

    // stage 2: register bits {8..4} -> obs 7..10 (pairs (8,7)..(5,4))
    {
        const int base = ((tid >> 4) << 9) | (tid & 15);
        #pragma unroll
        for (int r = 0; r < 32; r++) v[r] = t[SW(base | (r << 4))];
        float s7  = wred(obs_reg<4>(v, A, D, 7));
        float s8  = wred(obs_reg<3>(v, A, D, 8));
        float s9  = wred(obs_reg<2>(v, A, D, 9));
        float s10 = wred(obs_reg<1>(v, A, D, 10));
        if (lane == 0) { red[4][warp]=s7; red[5][warp]=s8; red[6][warp]=s9; red[7][warp]=s10; }
    }

    // stage 3: register bits {4..0} -> obs 11..14 (pairs (4,3)..(1,0)); smem read-only
    {
        #pragma unroll
        for (int r = 0; r < 32; r++) v[r] = t[SW((tid << 5) | r)];
        float s11 = wred(obs_reg<4>(v, A, D, 11));
        float s12 = wred(obs_reg<3>(v, A, D, 12));
        float s13 = wred(obs_reg<2>(v, A, D, 13));
        float s14 = wred(obs_reg<1>(v, A, D, 14));
        if (lane == 0) { red[8][warp]=s11; red[9][warp]=s12; red[10][warp]=s13; red[11][warp]=s14; }
    }
    __syncthreads();
    if (tid < 12) {
        float s = 0.f;
        #pragma unroll
        for (int wg = 0; wg < 8; wg++) s += red[tid][wg];
        g_part[(b * NOBS + (tid + 3)) * 8 + f] = s;   // deterministic
    }
}

// ---------------- head: out[b,o] = sum_w E[b,w] * hw[o,w] + hb[o] ----------------

__global__ void __launch_bounds__(THREADS)
head_kernel(const float* __restrict__ hw, const float* __restrict__ hb,
            float* __restrict__ out) {
    const int i = blockIdx.x * blockDim.x + threadIdx.x;   // 16384 threads
    const int b = i >> 6;
    const int o = i & 63;
    float acc = hb[o];
    #pragma unroll
    for (int w = 0; w < NOBS; w++) {
        float e = 0.f;
        #pragma unroll
        for (int f = 0; f < 8; f++) e += g_part[(b * NOBS + w) * 8 + f];
        acc += e * hw[o * NOBS + w];
    }
    out[i] = acc;
}

// ---------------- launcher ----------------

extern "C" void kernel_launch(void* const* d_in, const int* in_sizes, int n_in,
                              void* d_out, int out_size) {
    const float* x   = (const float*)d_in[0];   // (256,64)
    const float* A   = (const float*)d_in[1];   // (15,6)
    // d_in[2] = B: unused (imaginary part cancels for a real state)
    const float* D   = (const float*)d_in[3];   // (15,4)
    const float* var = (const float*)d_in[4];   // (4,16)
    const float* hw  = (const float*)d_in[5];   // (64,15)
    const float* hb  = (const float*)d_in[6];   // (64,)
    float* out = (float*)d_out;                 // (256,64)

    const int GRID = BSZ * 8;                   // 2048 CTAs per pass

    // layer 0: product-state init (all 16 RYs folded in) + ladder
    pass_a<<<GRID, THREADS>>>(x, var, 0, 1);
    pass_b<<<GRID, THREADS>>>(x, var, A, D, 0, 1, 0);
    // layers 1..6 (enc1, enc2, enc3+vqc0 merged, vqc1, vqc2, vqc3)
    for (int L = 1; L <= 6; L++) {
        pass_a<<<GRID, THREADS>>>(x, var, L, 0);
        pass_b<<<GRID, THREADS>>>(x, var, A, D, L, 0, L == 6);
    }

    measure_a<<<GRID, THREADS>>>(A, D);
    head_kernel<<<64, THREADS>>>(hw, hb, out);
}